// round 14
// baseline (speedup 1.0000x reference)
#include <cuda_runtime.h>
#include <cuda_bf16.h>

#define B_ 8
#define T_ 256
#define U_ 65
#define D_ 512
#define BTU_ (B_ * T_ * U_)
#define RSTRIDE 136              // floats per (b,t) row
#define PAD 66                   // zero pad rows in front (smem only)
#define RTOT 392                 // PAD + T + back pad

#define BIAS 10.0f
#define INV_LN2 1.4426950408889634f
#define LN2 0.6931471805599453f

// Row layout (RSTRIDE floats), pair-oriented:
//   [  0..  1] zeroPair (never written; lane0's u-1 reads land here)
//   [  2.. 67] oddPairs : slot i = (blank(t,2i+1), label(t,2i+1)), i=0..31;
//              slot 32 (offsets 66,67) stays 0
//   [ 68..133] evenPairs: slot i = (blank(t,2i), label(t,2i)), i=0..32
//   [134..135] pad = 0
__device__ float g_probs[B_ * T_ * RSTRIDE];

__device__ __forceinline__ float ex2f(float x) {
    float y; asm("ex2.approx.ftz.f32 %0, %1;" : "=f"(y) : "f"(x)); return y;
}
__device__ __forceinline__ float lg2f(float x) {
    float y; asm("lg2.approx.ftz.f32 %0, %1;" : "=f"(y) : "f"(x)); return y;
}
__device__ __forceinline__ float2 ld2(const float* p) {
    return *reinterpret_cast<const float2*>(p);
}

// ---------------------------------------------------------------------------
// Kernel 1: per-row logsumexp over D=512 -> biased linear probs, pair layout.
// __launch_bounds__(256, 8): <=32 regs -> 8 CTAs/SM -> 64 warps/SM -> enough
// MLP to reach the HBM roofline (~8TB/s) instead of the 6-CTA 6.4TB/s.
// ---------------------------------------------------------------------------
__global__ void __launch_bounds__(256, 8) lse_kernel(const float* __restrict__ logits,
                                                     const int* __restrict__ targets) {
    const int gw = (blockIdx.x * 256 + threadIdx.x) >> 5;
    const int lane = threadIdx.x & 31;
    if (gw >= BTU_) return;

    const float4* row4 = reinterpret_cast<const float4*>(logits + (size_t)gw * D_);
    const float4 v0 = row4[lane];
    const float4 v1 = row4[lane + 32];
    const float4 v2 = row4[lane + 64];
    const float4 v3 = row4[lane + 96];

    float m = v0.x;
    m = fmaxf(m, v0.y); m = fmaxf(m, v0.z); m = fmaxf(m, v0.w);
    m = fmaxf(m, v1.x); m = fmaxf(m, v1.y); m = fmaxf(m, v1.z); m = fmaxf(m, v1.w);
    m = fmaxf(m, v2.x); m = fmaxf(m, v2.y); m = fmaxf(m, v2.z); m = fmaxf(m, v2.w);
    m = fmaxf(m, v3.x); m = fmaxf(m, v3.y); m = fmaxf(m, v3.z); m = fmaxf(m, v3.w);
#pragma unroll
    for (int o = 16; o; o >>= 1) m = fmaxf(m, __shfl_xor_sync(0xffffffffu, m, o));

    float s = 0.f;
    s += __expf(v0.x - m) + __expf(v0.y - m) + __expf(v0.z - m) + __expf(v0.w - m);
    s += __expf(v1.x - m) + __expf(v1.y - m) + __expf(v1.z - m) + __expf(v1.w - m);
    s += __expf(v2.x - m) + __expf(v2.y - m) + __expf(v2.z - m) + __expf(v2.w - m);
    s += __expf(v3.x - m) + __expf(v3.y - m) + __expf(v3.z - m) + __expf(v3.w - m);
#pragma unroll
    for (int o = 16; o; o >>= 1) s += __shfl_xor_sync(0xffffffffu, s, o);

    const float lse = m + __logf(s);
    const float blankLogit = __shfl_sync(0xffffffffu, v3.w, 31);   // element 511

    if (lane == 0) {
        const int b = gw / (T_ * U_);
        const int rem = gw % (T_ * U_);
        const int t = rem / U_;
        const int u = rem % U_;
        const int lbl = (u < U_ - 1) ? targets[b * (U_ - 1) + u] : 0;
        const float labelLogit = __ldg(logits + (size_t)gw * D_ + lbl);
        const float pb = ex2f((blankLogit - lse) * INV_LN2 + BIAS);
        const float pl = ex2f((labelLogit - lse) * INV_LN2 + BIAS);
        const int base = (b * T_ + t) * RSTRIDE;
        if (u & 1) {          // oddPairs slot (u-1)/2 at offset 2+ (u-1) = u+1
            g_probs[base + u + 1] = pb;
            g_probs[base + u + 2] = pl;
        } else {              // evenPairs slot u/2 at offset 68 + u
            g_probs[base + 68 + u] = pb;
            g_probs[base + 69 + u] = pl;
        }
    }
}

// ---------------------------------------------------------------------------
// Kernel 2: bidirectional linear-domain DP, one CTA/batch, pair loads.
// Warp 0: alpha forward diag 1..dM (5 loads/diag). Warp 1: beta backward
// diag dE-1..dM (3 loads/diag). Combine on cut: loss = sum alpha*beta.
// ---------------------------------------------------------------------------
extern __shared__ float s_dyn[];

__global__ void __launch_bounds__(128) dp_kernel(const int* __restrict__ srcLen,
                                                 const int* __restrict__ tgtLen,
                                                 float* __restrict__ out) {
    __shared__ float xch[97];    // bE[32], bO[32], bX[32], shiftB

    const int b = blockIdx.x;
    const int tid = threadIdx.x;
    const int wid = tid >> 5;
    const int lane = tid & 31;

    float* sP = s_dyn;   // [RTOT * RSTRIDE]

    {   // Zero pads; copy valid rows (float4 contiguous).
        const float4 zr = make_float4(0.f, 0.f, 0.f, 0.f);
        float4* s4 = reinterpret_cast<float4*>(sP);
        const int rowQ = RSTRIDE / 4;                    // 34
        const int frontQ = PAD * rowQ;
        const int backStart = (PAD + T_) * rowQ;
        const int backQ = (RTOT - PAD - T_) * rowQ;
        for (int i = tid; i < frontQ; i += 128) s4[i] = zr;
        for (int i = tid; i < backQ; i += 128) s4[backStart + i] = zr;
        const float4* g4 = reinterpret_cast<const float4*>(g_probs + (size_t)b * T_ * RSTRIDE);
#pragma unroll 4
        for (int i = tid; i < T_ * rowQ; i += 128) s4[frontQ + i] = g4[i];
    }
    __syncthreads();
    if (wid >= 2) return;

    const int tE = srcLen[b] - 1;
    const int uE = tgtLen[b];
    const int dE = tE + uE;
    const int dM = (dE + 1) >> 1;          // cut diagonal

    const int rb = (PAD + tE) * RSTRIDE;
    const float BtEuE = (uE & 1) ? sP[rb + uE + 1] : sP[rb + 68 + uE];

    if (dE == 0) {
        if (wid == 0 && lane == 0) out[b] = -LN2 * (lg2f(BtEuE) - BIAS);
        return;
    }

    const int u0 = 2 * lane;

#define RENORM3(x, y, z, shift)                                                   \
    {                                                                             \
        float mval = fmaxf(x, fmaxf(y, z));                                       \
        for (int o = 16; o; o >>= 1)                                              \
            mval = fmaxf(mval, __shfl_xor_sync(0xffffffffu, mval, o));            \
        const int e = ilogbf(mval);                                               \
        const float sc = __uint_as_float((unsigned)(127 - e) << 23);              \
        x *= sc; y *= sc; z *= sc;                                                \
        shift += (float)e;                                                        \
    }

    if (wid == 1) {
        // ---------------- beta backward: diag dE-1 -> dM, 3 loads/diag ------
        float bE = 0.f, bO = 0.f, bX = 0.f, shiftB = 0.f;
        if (uE == 64)      { if (lane == 31)        bX = BtEuE; }
        else if (uE & 1)   { if (lane == (uE >> 1)) bO = BtEuE; }
        else               { if (lane == (uE >> 1)) bE = BtEuE; }

        // Pointers at diag d = dE-1 (advance -RSTRIDE per iteration):
        int d = dE - 1;
        const float* qE = sP + (PAD + d - u0) * RSTRIDE + 68 + u0;      // evenPair(t0, l)
        const float* qO = sP + (PAD + d - 1 - u0) * RSTRIDE + 2 + u0;   // oddPair(t0-1, l)
        const float* qX = sP + (PAD + d - 64) * RSTRIDE + 132;          // blank(d-64, 64)

        float2 cE = ld2(qE), cO = ld2(qO);
        float cX = *qX;

        int k = 0;
        for (; d >= dM; --d) {
            qE -= RSTRIDE; qO -= RSTRIDE; qX -= RSTRIDE;
            const float2 nE2 = ld2(qE), nO2 = ld2(qO);
            const float nX2 = *qX;

            float sh = __shfl_down_sync(0xffffffffu, bE, 1);
            sh = (lane == 31) ? bX : sh;                 // u=63's right neighbor is u=64

            const float rE = fmaf(bE, cE.x, bO * cE.y);  // B(t,u)*beta(t+1,u)+L(t,u)*beta(t,u+1)
            const float rO = fmaf(bO, cO.x, sh * cO.y);
            const float rX = bX * cX;                    // u=64: blank-only descent
            bE = rE; bO = rO; bX = rX;

            cE = nE2; cO = nO2; cX = nX2;

            if ((++k & 31) == 0) RENORM3(bE, bO, bX, shiftB)
        }

        xch[lane] = bE;
        xch[32 + lane] = bO;
        xch[64 + lane] = bX;
        if (lane == 0) xch[96] = shiftB;
        asm volatile("bar.sync 1, 64;" ::: "memory");
        return;
    }

    // ---------------- alpha forward: diag 1 -> dM, 5 loads/diag --------------
    float aE = (lane == 0) ? 1.0f : 0.0f;
    float aO = 0.f;
    float aX = 0.f;
    float shiftF = 0.f;

    // Pointers at diag d=1 (advance +RSTRIDE per diag):
    const float* pE = sP + (PAD - u0) * RSTRIDE + 68 + u0;       // evenPair(t0-1, l): B0, L1
    const float* pL = sP + (PAD + 1 - u0) * RSTRIDE + u0;        // oddPair(t0, l-1): .y = L0; lane0 -> zeroPair
    const float* pB = sP + (PAD - 1 - u0) * RSTRIDE + 2 + u0;    // oddPair(t0-2, l): .x = B1
    const float* pX = sP + (PAD + 1 - 65) * RSTRIDE + 132;       // blank(d-65, 64)
    const float* pXL = sP + (PAD + 1 - 64) * RSTRIDE + 65;       // label(d-64, 63) = oddPair slot31 .y

    float2 cE = ld2(pE), cL = ld2(pL), cB = ld2(pB);
    float cX = *pX, cXL = *pXL;

    for (int d = 1; d <= dM; ++d) {
        pE += RSTRIDE; pL += RSTRIDE; pB += RSTRIDE; pX += RSTRIDE; pXL += RSTRIDE;
        const float2 nE2 = ld2(pE), nL2 = ld2(pL), nB2 = ld2(pB);
        const float nX2 = *pX, nXL = *pXL;

        const float nbr = __shfl_up_sync(0xffffffffu, aO, 1);   // lane0: zeroPair kills it

        const float rE = fmaf(aE, cE.x, nbr * cL.y);
        const float rO = fmaf(aO, cB.x, aE * cE.y);
        const float rX = fmaf(aX, cX, aO * cXL);
        aE = rE; aO = rO; aX = rX;

        cE = nE2; cL = nL2; cB = nB2; cX = nX2; cXL = nXL;

        if ((d & 31) == 0) RENORM3(aE, aO, aX, shiftF)
    }

    asm volatile("bar.sync 1, 64;" ::: "memory");

    // Cut combine: loss = sum over diag-dM cells of alpha*beta.
    float s = aE * xch[lane] + aO * xch[32 + lane] + aX * xch[64 + lane];
#pragma unroll
    for (int o = 16; o; o >>= 1) s += __shfl_xor_sync(0xffffffffu, s, o);

    if (lane == 0) {
        const float shiftB = xch[96];
        out[b] = -LN2 * (lg2f(s) + shiftF + shiftB - BIAS * (float)(dE + 1));
    }
#undef RENORM3
}

// ---------------------------------------------------------------------------
extern "C" void kernel_launch(void* const* d_in, const int* in_sizes, int n_in,
                              void* d_out, int out_size) {
    const float* logits = (const float*)d_in[0];
    const int* targets = (const int*)d_in[1];
    const int* srcLen = (const int*)d_in[2];
    const int* tgtLen = (const int*)d_in[3];
    float* out = (float*)d_out;

    lse_kernel<<<BTU_ / 8, 256>>>(logits, targets);

    const int smemBytes = RTOT * RSTRIDE * (int)sizeof(float);  // 213248 B
    cudaFuncSetAttribute(dp_kernel, cudaFuncAttributeMaxDynamicSharedMemorySize, smemBytes);
    dp_kernel<<<B_, 128, smemBytes>>>(srcLen, tgtLen, out);
}

// round 15
// speedup vs baseline: 1.0518x; 1.0518x over previous
#include <cuda_runtime.h>
#include <cuda_bf16.h>

#define B_ 8
#define T_ 256
#define U_ 65
#define D_ 512
#define BTU_ (B_ * T_ * U_)
#define RSTRIDE 136              // floats per (b,t) row
#define PAD 66                   // zero pad rows in front (smem only)
#define RTOT 392                 // PAD + T + 70 back-pad rows

#define BIAS 10.0f
#define INV_LN2 1.4426950408889634f
#define LN2 0.6931471805599453f

// Plane-split row layout (RSTRIDE floats):
//   [  0.. 33] labelOdd : slot i = label(t, 2i-1), i=1..32; slots 0,33 stay 0
//   [ 34.. 66] blankEven: slot i = blank(t, 2i),   i=0..32
//   [ 67.. 99] blankOdd : slot i = blank(t, 2i+1), i=0..31; slot 32 stays 0
//   [100..132] labelEven: slot i = label(t, 2i),   i=0..32
//   [133..135] pad = 0
__device__ float g_probs[B_ * T_ * RSTRIDE];

__device__ __forceinline__ float ex2f(float x) {
    float y; asm("ex2.approx.ftz.f32 %0, %1;" : "=f"(y) : "f"(x)); return y;
}
__device__ __forceinline__ float lg2f(float x) {
    float y; asm("lg2.approx.ftz.f32 %0, %1;" : "=f"(y) : "f"(x)); return y;
}

// ---------------------------------------------------------------------------
// Kernel 1: per-row logsumexp over D=512 -> biased linear probs, plane-split.
// One warp per row; HBM-bound (proven ~42us shape — R13 verbatim).
// ---------------------------------------------------------------------------
__global__ void __launch_bounds__(256) lse_kernel(const float* __restrict__ logits,
                                                  const int* __restrict__ targets) {
    const int gw = (blockIdx.x * 256 + threadIdx.x) >> 5;
    const int lane = threadIdx.x & 31;
    if (gw >= BTU_) return;

    const float4* row4 = reinterpret_cast<const float4*>(logits + (size_t)gw * D_);
    const float4 v0 = row4[lane];
    const float4 v1 = row4[lane + 32];
    const float4 v2 = row4[lane + 64];
    const float4 v3 = row4[lane + 96];

    float m = v0.x;
    m = fmaxf(m, v0.y); m = fmaxf(m, v0.z); m = fmaxf(m, v0.w);
    m = fmaxf(m, v1.x); m = fmaxf(m, v1.y); m = fmaxf(m, v1.z); m = fmaxf(m, v1.w);
    m = fmaxf(m, v2.x); m = fmaxf(m, v2.y); m = fmaxf(m, v2.z); m = fmaxf(m, v2.w);
    m = fmaxf(m, v3.x); m = fmaxf(m, v3.y); m = fmaxf(m, v3.z); m = fmaxf(m, v3.w);
#pragma unroll
    for (int o = 16; o; o >>= 1) m = fmaxf(m, __shfl_xor_sync(0xffffffffu, m, o));

    float s = 0.f;
    s += __expf(v0.x - m) + __expf(v0.y - m) + __expf(v0.z - m) + __expf(v0.w - m);
    s += __expf(v1.x - m) + __expf(v1.y - m) + __expf(v1.z - m) + __expf(v1.w - m);
    s += __expf(v2.x - m) + __expf(v2.y - m) + __expf(v2.z - m) + __expf(v2.w - m);
    s += __expf(v3.x - m) + __expf(v3.y - m) + __expf(v3.z - m) + __expf(v3.w - m);
#pragma unroll
    for (int o = 16; o; o >>= 1) s += __shfl_xor_sync(0xffffffffu, s, o);

    const float lse = m + __logf(s);
    const float blankLogit = __shfl_sync(0xffffffffu, v3.w, 31);   // element 511

    if (lane == 0) {
        const int b = gw / (T_ * U_);
        const int rem = gw % (T_ * U_);
        const int t = rem / U_;
        const int u = rem % U_;
        const int lbl = (u < U_ - 1) ? targets[b * (U_ - 1) + u] : 0;
        const float labelLogit = __ldg(logits + (size_t)gw * D_ + lbl);
        const float pb = ex2f((blankLogit - lse) * INV_LN2 + BIAS);
        const float pl = ex2f((labelLogit - lse) * INV_LN2 + BIAS);
        const int base = (b * T_ + t) * RSTRIDE;
        if (u & 1) {
            g_probs[base + 0  + ((u + 1) >> 1)] = pl;   // labelOdd
            g_probs[base + 67 + ((u - 1) >> 1)] = pb;   // blankOdd
        } else {
            g_probs[base + 34  + (u >> 1)] = pb;        // blankEven
            g_probs[base + 100 + (u >> 1)] = pl;        // labelEven
        }
    }
}

// ---------------------------------------------------------------------------
// Kernel 2: bidirectional linear-domain DP, one CTA/batch.
// Warp 0: alpha forward diag 1..dM; warp 1: beta backward diag dE-1..dM.
// Chunks of 32 diagonals, unrolled x16 with immediate-offset LDS and no
// branches in the body; renorm once per chunk. launch_bounds(128,1) frees
// the register budget so ptxas can front-issue the loads.
// ---------------------------------------------------------------------------
extern __shared__ float s_dyn[];

__global__ void __launch_bounds__(128, 1) dp_kernel(const int* __restrict__ srcLen,
                                                    const int* __restrict__ tgtLen,
                                                    float* __restrict__ out) {
    __shared__ float xch[97];    // bE[32], bO[32], bX[32], shiftB

    const int b = blockIdx.x;
    const int tid = threadIdx.x;
    const int wid = tid >> 5;
    const int lane = tid & 31;

    float* sP = s_dyn;   // [RTOT * RSTRIDE]

    {   // Zero pads; copy valid rows (float4 contiguous).
        const float4 zr = make_float4(0.f, 0.f, 0.f, 0.f);
        float4* s4 = reinterpret_cast<float4*>(sP);
        const int rowQ = RSTRIDE / 4;                    // 34
        const int frontQ = PAD * rowQ;
        const int backStart = (PAD + T_) * rowQ;
        const int backQ = (RTOT - PAD - T_) * rowQ;
        for (int i = tid; i < frontQ; i += 128) s4[i] = zr;
        for (int i = tid; i < backQ; i += 128) s4[backStart + i] = zr;
        const float4* g4 = reinterpret_cast<const float4*>(g_probs + (size_t)b * T_ * RSTRIDE);
#pragma unroll 4
        for (int i = tid; i < T_ * rowQ; i += 128) s4[frontQ + i] = g4[i];
    }
    __syncthreads();
    if (wid >= 2) return;

    const int tE = srcLen[b] - 1;
    const int uE = tgtLen[b];
    const int dE = tE + uE;
    const int dM = (dE + 1) >> 1;          // cut diagonal

    const int rb = (PAD + tE) * RSTRIDE;
    const float BtEuE = (uE & 1) ? sP[rb + 67 + ((uE - 1) >> 1)]
                                 : sP[rb + 34 + (uE >> 1)];

    if (dE == 0) {
        if (wid == 0 && lane == 0) out[b] = -LN2 * (lg2f(BtEuE) - BIAS);
        return;
    }

    const int u0 = 2 * lane;

#define RENORM3(x, y, z, shift)                                                   \
    {                                                                             \
        float mval = fmaxf(x, fmaxf(y, z));                                       \
        for (int o = 16; o; o >>= 1)                                              \
            mval = fmaxf(mval, __shfl_xor_sync(0xffffffffu, mval, o));            \
        const int e = ilogbf(mval);                                               \
        const float sc = __uint_as_float((unsigned)(127 - e) << 23);              \
        x *= sc; y *= sc; z *= sc;                                                \
        shift += (float)e;                                                        \
    }

    if (wid == 1) {
        // ---------------- beta backward: diag dE-1 -> dM ----------------
        float bE = 0.f, bO = 0.f, bX = 0.f, shiftB = 0.f;
        if (uE == 64)      { if (lane == 31)        bX = BtEuE; }
        else if (uE & 1)   { if (lane == (uE >> 1)) bO = BtEuE; }
        else               { if (lane == (uE >> 1)) bE = BtEuE; }

        // Per-lane base addresses at the current chunk-top diag d:
        // load for diag (d - k) is at base[-k*RSTRIDE].
        int d = dE - 1;
        const float* aB0 = sP + (PAD + d - u0) * RSTRIDE + 34 + lane;      // blank(t0, u0)
        const float* aL0 = sP + (PAD + d - u0) * RSTRIDE + 100 + lane;     // label(t0, u0)
        const float* aB1 = sP + (PAD + d - 1 - u0) * RSTRIDE + 67 + lane;  // blank(t1, u0+1)
        const float* aL1 = sP + (PAD + d - 1 - u0) * RSTRIDE + 1 + lane;   // label(t1, u0+1)
        const float* aBx = sP + (PAD + d - 64) * RSTRIDE + 66;             // blank(d-64, 64)

#define BSTEP(K)                                                         \
        {                                                                \
            const float B0 = aB0[-(K) * RSTRIDE], L0 = aL0[-(K) * RSTRIDE]; \
            const float B1 = aB1[-(K) * RSTRIDE], L1 = aL1[-(K) * RSTRIDE]; \
            const float Bx = aBx[-(K) * RSTRIDE];                        \
            float sh = __shfl_down_sync(0xffffffffu, bE, 1);             \
            sh = (lane == 31) ? bX : sh;                                 \
            const float rE = fmaf(bE, B0, bO * L0);                      \
            const float rO = fmaf(bO, B1, sh * L1);                      \
            const float rX = bX * Bx;                                    \
            bE = rE; bO = rO; bX = rX;                                   \
        }

        while (d - 31 >= dM) {            // full 32-diag chunks
#pragma unroll
            for (int k = 0; k < 32; ++k) BSTEP(k)
            aB0 -= 32 * RSTRIDE; aL0 -= 32 * RSTRIDE; aB1 -= 32 * RSTRIDE;
            aL1 -= 32 * RSTRIDE; aBx -= 32 * RSTRIDE;
            d -= 32;
            RENORM3(bE, bO, bX, shiftB)
        }
        while (d >= dM) {                 // tail (<32 diags; renorm-safe)
            BSTEP(0)
            aB0 -= RSTRIDE; aL0 -= RSTRIDE; aB1 -= RSTRIDE;
            aL1 -= RSTRIDE; aBx -= RSTRIDE;
            --d;
        }
#undef BSTEP

        xch[lane] = bE;
        xch[32 + lane] = bO;
        xch[64 + lane] = bX;
        if (lane == 0) xch[96] = shiftB;
        asm volatile("bar.sync 1, 64;" ::: "memory");
        return;
    }

    // ---------------- alpha forward: diag 1 -> dM (warp 0) ----------------
    float aEv = (lane == 0) ? 1.0f : 0.0f;
    float aOv = 0.f;
    float aXv = 0.f;
    float shiftF = 0.f;

    // Per-lane base addresses at chunk-start diag d; diag (d + k) at +k*RSTRIDE.
    int d = 1;
    const float* aB0 = sP + (PAD + d - 1 - u0) * RSTRIDE + 34 + lane;   // blank(t0-1, u0)
    const float* aL0 = sP + (PAD + d - u0) * RSTRIDE + 0 + lane;        // label(t0, u0-1); lane0 -> 0-slot
    const float* aB1 = sP + (PAD + d - 2 - u0) * RSTRIDE + 67 + lane;   // blank(t0-2, u0+1)
    const float* aL1 = sP + (PAD + d - 1 - u0) * RSTRIDE + 100 + lane;  // label(t0-1, u0)
    const float* aBx = sP + (PAD + d - 65) * RSTRIDE + 66;              // blank(d-65, 64)
    const float* aLx = sP + (PAD + d - 64) * RSTRIDE + 32;              // label(d-64, 63)

#define ASTEP(K)                                                         \
    {                                                                    \
        const float B0 = aB0[(K) * RSTRIDE], L0 = aL0[(K) * RSTRIDE];    \
        const float B1 = aB1[(K) * RSTRIDE], L1 = aL1[(K) * RSTRIDE];    \
        const float Bx = aBx[(K) * RSTRIDE], Lx = aLx[(K) * RSTRIDE];    \
        const float nbr = __shfl_up_sync(0xffffffffu, aOv, 1);           \
        const float rE = fmaf(aEv, B0, nbr * L0);                        \
        const float rO = fmaf(aOv, B1, aEv * L1);                        \
        const float rX = fmaf(aXv, Bx, aOv * Lx);                        \
        aEv = rE; aOv = rO; aXv = rX;                                    \
    }

    while (d + 31 <= dM) {                // full 32-diag chunks
#pragma unroll
        for (int k = 0; k < 32; ++k) ASTEP(k)
        aB0 += 32 * RSTRIDE; aL0 += 32 * RSTRIDE; aB1 += 32 * RSTRIDE;
        aL1 += 32 * RSTRIDE; aBx += 32 * RSTRIDE; aLx += 32 * RSTRIDE;
        d += 32;
        RENORM3(aEv, aOv, aXv, shiftF)
    }
    while (d <= dM) {                     // tail (<32 diags; renorm-safe)
        ASTEP(0)
        aB0 += RSTRIDE; aL0 += RSTRIDE; aB1 += RSTRIDE;
        aL1 += RSTRIDE; aBx += RSTRIDE; aLx += RSTRIDE;
        ++d;
    }
#undef ASTEP

    asm volatile("bar.sync 1, 64;" ::: "memory");

    // Cut combine: loss = sum over diag-dM cells of alpha*beta.
    float s = aEv * xch[lane] + aOv * xch[32 + lane] + aXv * xch[64 + lane];
#pragma unroll
    for (int o = 16; o; o >>= 1) s += __shfl_xor_sync(0xffffffffu, s, o);

    if (lane == 0) {
        const float shiftB = xch[96];
        out[b] = -LN2 * (lg2f(s) + shiftF + shiftB - BIAS * (float)(dE + 1));
    }
#undef RENORM3
}

// ---------------------------------------------------------------------------
extern "C" void kernel_launch(void* const* d_in, const int* in_sizes, int n_in,
                              void* d_out, int out_size) {
    const float* logits = (const float*)d_in[0];
    const int* targets = (const int*)d_in[1];
    const int* srcLen = (const int*)d_in[2];
    const int* tgtLen = (const int*)d_in[3];
    float* out = (float*)d_out;

    lse_kernel<<<BTU_ / 8, 256>>>(logits, targets);

    const int smemBytes = RTOT * RSTRIDE * (int)sizeof(float);  // 213248 B
    cudaFuncSetAttribute(dp_kernel, cudaFuncAttributeMaxDynamicSharedMemorySize, smemBytes);
    dp_kernel<<<B_, 128, smemBytes>>>(srcLen, tgtLen, out);
}

// round 16
// speedup vs baseline: 1.1863x; 1.1278x over previous
#include <cuda_runtime.h>
#include <cuda_bf16.h>

#define B_ 8
#define T_ 256
#define U_ 65
#define D_ 512
#define BTU_ (B_ * T_ * U_)
#define RSTRIDE 136              // floats per (b,t) row
#define PAD 66                   // zero pad rows in front (smem only)
#define RTOT 392                 // PAD + T + 70 back-pad rows

#define DPTHR 512                // dp block size (16 warps stage, 2 compute)

#define BIAS 10.0f
#define INV_LN2 1.4426950408889634f
#define LN2 0.6931471805599453f

// Plane-split row layout (RSTRIDE floats):
//   [  0.. 33] labelOdd : slot i = label(t, 2i-1), i=1..32; slots 0,33 stay 0
//   [ 34.. 66] blankEven: slot i = blank(t, 2i),   i=0..32
//   [ 67.. 99] blankOdd : slot i = blank(t, 2i+1), i=0..31; slot 32 stays 0
//   [100..132] labelEven: slot i = label(t, 2i),   i=0..32
//   [133..135] pad = 0
__device__ float g_probs[B_ * T_ * RSTRIDE];

__device__ __forceinline__ float ex2f(float x) {
    float y; asm("ex2.approx.ftz.f32 %0, %1;" : "=f"(y) : "f"(x)); return y;
}
__device__ __forceinline__ float lg2f(float x) {
    float y; asm("lg2.approx.ftz.f32 %0, %1;" : "=f"(y) : "f"(x)); return y;
}

// ---------------------------------------------------------------------------
// Kernel 1: per-row logsumexp over D=512 -> biased linear probs, plane-split.
// One warp per row; HBM-bound (proven ~42us shape — unchanged).
// ---------------------------------------------------------------------------
__global__ void __launch_bounds__(256) lse_kernel(const float* __restrict__ logits,
                                                  const int* __restrict__ targets) {
    const int gw = (blockIdx.x * 256 + threadIdx.x) >> 5;
    const int lane = threadIdx.x & 31;
    if (gw >= BTU_) return;

    const float4* row4 = reinterpret_cast<const float4*>(logits + (size_t)gw * D_);
    const float4 v0 = row4[lane];
    const float4 v1 = row4[lane + 32];
    const float4 v2 = row4[lane + 64];
    const float4 v3 = row4[lane + 96];

    float m = v0.x;
    m = fmaxf(m, v0.y); m = fmaxf(m, v0.z); m = fmaxf(m, v0.w);
    m = fmaxf(m, v1.x); m = fmaxf(m, v1.y); m = fmaxf(m, v1.z); m = fmaxf(m, v1.w);
    m = fmaxf(m, v2.x); m = fmaxf(m, v2.y); m = fmaxf(m, v2.z); m = fmaxf(m, v2.w);
    m = fmaxf(m, v3.x); m = fmaxf(m, v3.y); m = fmaxf(m, v3.z); m = fmaxf(m, v3.w);
#pragma unroll
    for (int o = 16; o; o >>= 1) m = fmaxf(m, __shfl_xor_sync(0xffffffffu, m, o));

    float s = 0.f;
    s += __expf(v0.x - m) + __expf(v0.y - m) + __expf(v0.z - m) + __expf(v0.w - m);
    s += __expf(v1.x - m) + __expf(v1.y - m) + __expf(v1.z - m) + __expf(v1.w - m);
    s += __expf(v2.x - m) + __expf(v2.y - m) + __expf(v2.z - m) + __expf(v2.w - m);
    s += __expf(v3.x - m) + __expf(v3.y - m) + __expf(v3.z - m) + __expf(v3.w - m);
#pragma unroll
    for (int o = 16; o; o >>= 1) s += __shfl_xor_sync(0xffffffffu, s, o);

    const float lse = m + __logf(s);
    const float blankLogit = __shfl_sync(0xffffffffu, v3.w, 31);   // element 511

    if (lane == 0) {
        const int b = gw / (T_ * U_);
        const int rem = gw % (T_ * U_);
        const int t = rem / U_;
        const int u = rem % U_;
        const int lbl = (u < U_ - 1) ? targets[b * (U_ - 1) + u] : 0;
        const float labelLogit = __ldg(logits + (size_t)gw * D_ + lbl);
        const float pb = ex2f((blankLogit - lse) * INV_LN2 + BIAS);
        const float pl = ex2f((labelLogit - lse) * INV_LN2 + BIAS);
        const int base = (b * T_ + t) * RSTRIDE;
        if (u & 1) {
            g_probs[base + 0  + ((u + 1) >> 1)] = pl;   // labelOdd
            g_probs[base + 67 + ((u - 1) >> 1)] = pb;   // blankOdd
        } else {
            g_probs[base + 34  + (u >> 1)] = pb;        // blankEven
            g_probs[base + 100 + (u >> 1)] = pl;        // labelEven
        }
    }
}

// ---------------------------------------------------------------------------
// Kernel 2: bidirectional linear-domain DP, one CTA/batch, 512 threads.
// All 16 warps stage the tile (4x the in-flight bytes of R15 -> ~2us);
// then warp 0 runs alpha forward (diag 1..dM) and warp 1 runs beta backward
// (diag dE-1..dM); combine on the cut. DP body: 32-diag unrolled chunks,
// immediate-offset LDS, renorm once per chunk.
// ---------------------------------------------------------------------------
extern __shared__ float s_dyn[];

__global__ void __launch_bounds__(DPTHR, 1) dp_kernel(const int* __restrict__ srcLen,
                                                      const int* __restrict__ tgtLen,
                                                      float* __restrict__ out) {
    __shared__ float xch[97];    // bE[32], bO[32], bX[32], shiftB

    const int b = blockIdx.x;
    const int tid = threadIdx.x;
    const int wid = tid >> 5;
    const int lane = tid & 31;

    float* sP = s_dyn;   // [RTOT * RSTRIDE]

    {   // Zero pads; copy valid rows (float4 contiguous) with 512 threads.
        const float4 zr = make_float4(0.f, 0.f, 0.f, 0.f);
        float4* s4 = reinterpret_cast<float4*>(sP);
        const int rowQ = RSTRIDE / 4;                    // 34
        const int frontQ = PAD * rowQ;                   // 2244
        const int backStart = (PAD + T_) * rowQ;
        const int backQ = (RTOT - PAD - T_) * rowQ;
        for (int i = tid; i < frontQ; i += DPTHR) s4[i] = zr;
        for (int i = tid; i < backQ; i += DPTHR) s4[backStart + i] = zr;
        const float4* g4 = reinterpret_cast<const float4*>(g_probs + (size_t)b * T_ * RSTRIDE);
#pragma unroll 4
        for (int i = tid; i < T_ * rowQ; i += DPTHR) s4[frontQ + i] = g4[i];
    }
    __syncthreads();
    if (wid >= 2) return;

    const int tE = srcLen[b] - 1;
    const int uE = tgtLen[b];
    const int dE = tE + uE;
    const int dM = (dE + 1) >> 1;          // cut diagonal

    const int rb = (PAD + tE) * RSTRIDE;
    const float BtEuE = (uE & 1) ? sP[rb + 67 + ((uE - 1) >> 1)]
                                 : sP[rb + 34 + (uE >> 1)];

    if (dE == 0) {
        if (wid == 0 && lane == 0) out[b] = -LN2 * (lg2f(BtEuE) - BIAS);
        return;
    }

    const int u0 = 2 * lane;

#define RENORM3(x, y, z, shift)                                                   \
    {                                                                             \
        float mval = fmaxf(x, fmaxf(y, z));                                       \
        for (int o = 16; o; o >>= 1)                                              \
            mval = fmaxf(mval, __shfl_xor_sync(0xffffffffu, mval, o));            \
        const int e = ilogbf(mval);                                               \
        const float sc = __uint_as_float((unsigned)(127 - e) << 23);              \
        x *= sc; y *= sc; z *= sc;                                                \
        shift += (float)e;                                                        \
    }

    if (wid == 1) {
        // ---------------- beta backward: diag dE-1 -> dM ----------------
        float bE = 0.f, bO = 0.f, bX = 0.f, shiftB = 0.f;
        if (uE == 64)      { if (lane == 31)        bX = BtEuE; }
        else if (uE & 1)   { if (lane == (uE >> 1)) bO = BtEuE; }
        else               { if (lane == (uE >> 1)) bE = BtEuE; }

        int d = dE - 1;
        const float* aB0 = sP + (PAD + d - u0) * RSTRIDE + 34 + lane;      // blank(t0, u0)
        const float* aL0 = sP + (PAD + d - u0) * RSTRIDE + 100 + lane;     // label(t0, u0)
        const float* aB1 = sP + (PAD + d - 1 - u0) * RSTRIDE + 67 + lane;  // blank(t1, u0+1)
        const float* aL1 = sP + (PAD + d - 1 - u0) * RSTRIDE + 1 + lane;   // label(t1, u0+1)
        const float* aBx = sP + (PAD + d - 64) * RSTRIDE + 66;             // blank(d-64, 64)

#define BSTEP(K)                                                         \
        {                                                                \
            const float B0 = aB0[-(K) * RSTRIDE], L0 = aL0[-(K) * RSTRIDE]; \
            const float B1 = aB1[-(K) * RSTRIDE], L1 = aL1[-(K) * RSTRIDE]; \
            const float Bx = aBx[-(K) * RSTRIDE];                        \
            float sh = __shfl_down_sync(0xffffffffu, bE, 1);             \
            sh = (lane == 31) ? bX : sh;                                 \
            const float rE = fmaf(bE, B0, bO * L0);                      \
            const float rO = fmaf(bO, B1, sh * L1);                      \
            const float rX = bX * Bx;                                    \
            bE = rE; bO = rO; bX = rX;                                   \
        }

        while (d - 31 >= dM) {
#pragma unroll
            for (int k = 0; k < 32; ++k) BSTEP(k)
            aB0 -= 32 * RSTRIDE; aL0 -= 32 * RSTRIDE; aB1 -= 32 * RSTRIDE;
            aL1 -= 32 * RSTRIDE; aBx -= 32 * RSTRIDE;
            d -= 32;
            RENORM3(bE, bO, bX, shiftB)
        }
        while (d >= dM) {
            BSTEP(0)
            aB0 -= RSTRIDE; aL0 -= RSTRIDE; aB1 -= RSTRIDE;
            aL1 -= RSTRIDE; aBx -= RSTRIDE;
            --d;
        }
#undef BSTEP

        xch[lane] = bE;
        xch[32 + lane] = bO;
        xch[64 + lane] = bX;
        if (lane == 0) xch[96] = shiftB;
        asm volatile("bar.sync 1, 64;" ::: "memory");
        return;
    }

    // ---------------- alpha forward: diag 1 -> dM (warp 0) ----------------
    float aEv = (lane == 0) ? 1.0f : 0.0f;
    float aOv = 0.f;
    float aXv = 0.f;
    float shiftF = 0.f;

    int d = 1;
    const float* aB0 = sP + (PAD + d - 1 - u0) * RSTRIDE + 34 + lane;   // blank(t0-1, u0)
    const float* aL0 = sP + (PAD + d - u0) * RSTRIDE + 0 + lane;        // label(t0, u0-1); lane0 -> 0-slot
    const float* aB1 = sP + (PAD + d - 2 - u0) * RSTRIDE + 67 + lane;   // blank(t0-2, u0+1)
    const float* aL1 = sP + (PAD + d - 1 - u0) * RSTRIDE + 100 + lane;  // label(t0-1, u0)
    const float* aBx = sP + (PAD + d - 65) * RSTRIDE + 66;              // blank(d-65, 64)
    const float* aLx = sP + (PAD + d - 64) * RSTRIDE + 32;              // label(d-64, 63)

#define ASTEP(K)                                                         \
    {                                                                    \
        const float B0 = aB0[(K) * RSTRIDE], L0 = aL0[(K) * RSTRIDE];    \
        const float B1 = aB1[(K) * RSTRIDE], L1 = aL1[(K) * RSTRIDE];    \
        const float Bx = aBx[(K) * RSTRIDE], Lx = aLx[(K) * RSTRIDE];    \
        const float nbr = __shfl_up_sync(0xffffffffu, aOv, 1);           \
        const float rE = fmaf(aEv, B0, nbr * L0);                        \
        const float rO = fmaf(aOv, B1, aEv * L1);                        \
        const float rX = fmaf(aXv, Bx, aOv * Lx);                        \
        aEv = rE; aOv = rO; aXv = rX;                                    \
    }

    while (d + 31 <= dM) {
#pragma unroll
        for (int k = 0; k < 32; ++k) ASTEP(k)
        aB0 += 32 * RSTRIDE; aL0 += 32 * RSTRIDE; aB1 += 32 * RSTRIDE;
        aL1 += 32 * RSTRIDE; aBx += 32 * RSTRIDE; aLx += 32 * RSTRIDE;
        d += 32;
        RENORM3(aEv, aOv, aXv, shiftF)
    }
    while (d <= dM) {
        ASTEP(0)
        aB0 += RSTRIDE; aL0 += RSTRIDE; aB1 += RSTRIDE;
        aL1 += RSTRIDE; aBx += RSTRIDE; aLx += RSTRIDE;
        ++d;
    }
#undef ASTEP

    asm volatile("bar.sync 1, 64;" ::: "memory");

    // Cut combine: loss = sum over diag-dM cells of alpha*beta.
    float s = aEv * xch[lane] + aOv * xch[32 + lane] + aXv * xch[64 + lane];
#pragma unroll
    for (int o = 16; o; o >>= 1) s += __shfl_xor_sync(0xffffffffu, s, o);

    if (lane == 0) {
        const float shiftB = xch[96];
        out[b] = -LN2 * (lg2f(s) + shiftF + shiftB - BIAS * (float)(dE + 1));
    }
#undef RENORM3
}

// ---------------------------------------------------------------------------
extern "C" void kernel_launch(void* const* d_in, const int* in_sizes, int n_in,
                              void* d_out, int out_size) {
    const float* logits = (const float*)d_in[0];
    const int* targets = (const int*)d_in[1];
    const int* srcLen = (const int*)d_in[2];
    const int* tgtLen = (const int*)d_in[3];
    float* out = (float*)d_out;

    lse_kernel<<<BTU_ / 8, 256>>>(logits, targets);

    const int smemBytes = RTOT * RSTRIDE * (int)sizeof(float);  // 213248 B
    cudaFuncSetAttribute(dp_kernel, cudaFuncAttributeMaxDynamicSharedMemorySize, smemBytes);
    dp_kernel<<<B_, DPTHR, smemBytes>>>(srcLen, tgtLen, out);
}